// round 1
// baseline (speedup 1.0000x reference)
#include <cuda_runtime.h>
#include <cstdint>

#define HIDDEN 2048
#define INTER  5504
#define TSTEPS 4
#define BSZ    2
#define SEQ    512
#define MROWS  (TSTEPS*BSZ*SEQ)   /* 4096 */
#define BSROWS (BSZ*SEQ)          /* 1024 */

// Scratch for gate/up projections (and C, written in place over G).
__device__ float g_G[(size_t)MROWS * INTER];
__device__ float g_U[(size_t)MROWS * INTER];

__device__ __forceinline__ uint32_t f2tf32(float x) {
    uint32_t r;
    asm("cvt.rna.tf32.f32 %0, %1;" : "=r"(r) : "f"(x));
    return r;
}

__device__ __forceinline__ void mma_tf32(float* d, const uint32_t* a, const uint32_t* b) {
    asm volatile(
        "mma.sync.aligned.m16n8k8.row.col.f32.tf32.tf32.f32 "
        "{%0,%1,%2,%3}, {%4,%5,%6,%7}, {%8,%9}, {%0,%1,%2,%3};\n"
        : "+f"(d[0]), "+f"(d[1]), "+f"(d[2]), "+f"(d[3])
        : "r"(a[0]), "r"(a[1]), "r"(a[2]), "r"(a[3]), "r"(b[0]), "r"(b[1]));
}

// C[m,n] = sum_k A[m,k] * B[n,k]
// A: M x K row-major, B: N x K row-major, C: M x N row-major.
// Requires: M % 128 == 0 (grid.y), N % 128 == 0 (grid.x), K % 32 == 0.
__global__ void __launch_bounds__(256, 1)
gemm_tn_kernel(const float* __restrict__ A, const float* __restrict__ B,
               float* __restrict__ C, int K, int N)
{
    // smem layout: [k4 (0..7)][m (0..127)] float4 atoms, XOR-swizzled: slot m ^ k4.
    __shared__ uint4 As4[8 * 128];
    __shared__ uint4 Bs4[8 * 128];
    uint32_t* Asw = reinterpret_cast<uint32_t*>(As4);
    uint32_t* Bsw = reinterpret_cast<uint32_t*>(Bs4);

    const int tid  = threadIdx.x;
    const int lane = tid & 31;
    const int warp = tid >> 5;
    const int wm   = warp & 1;   // 2 warp rows of 64
    const int wn   = warp >> 1;  // 4 warp cols of 32

    // Global load mapping: r = row-within-group (0..31), c = float4-col (0..7)
    const int r = tid >> 3;
    const int c = tid & 7;

    const size_t mBase = (size_t)blockIdx.y * 128;
    const size_t nBase = (size_t)blockIdx.x * 128;

    const float* Ag = A + (mBase + (size_t)r) * (size_t)K + (size_t)c * 4;
    const float* Bg = B + (nBase + (size_t)r) * (size_t)K + (size_t)c * 4;

    const int ntiles = K >> 5;

    float4 pa[4], pb[4];
    // Prologue: prefetch tile 0 into registers.
    #pragma unroll
    for (int it = 0; it < 4; ++it) {
        pa[it] = *(const float4*)(Ag + (size_t)(it * 32) * K);
        pb[it] = *(const float4*)(Bg + (size_t)(it * 32) * K);
    }

    float acc[4][4][4];
    #pragma unroll
    for (int i = 0; i < 4; ++i)
        #pragma unroll
        for (int j = 0; j < 4; ++j)
            #pragma unroll
            for (int q = 0; q < 4; ++q) acc[i][j][q] = 0.f;

    for (int kt = 0; kt < ntiles; ++kt) {
        // Store prefetched tile to smem (tf32 round + XOR swizzle).
        #pragma unroll
        for (int it = 0; it < 4; ++it) {
            const int m = it * 32 + r;
            As4[c * 128 + (m ^ c)] =
                make_uint4(f2tf32(pa[it].x), f2tf32(pa[it].y), f2tf32(pa[it].z), f2tf32(pa[it].w));
            Bs4[c * 128 + (m ^ c)] =
                make_uint4(f2tf32(pb[it].x), f2tf32(pb[it].y), f2tf32(pb[it].z), f2tf32(pb[it].w));
        }
        __syncthreads();

        // Issue next tile's global loads (overlap with compute below).
        if (kt + 1 < ntiles) {
            const float* Ag2 = Ag + (size_t)(kt + 1) * 32;
            const float* Bg2 = Bg + (size_t)(kt + 1) * 32;
            #pragma unroll
            for (int it = 0; it < 4; ++it) {
                pa[it] = *(const float4*)(Ag2 + (size_t)(it * 32) * K);
                pb[it] = *(const float4*)(Bg2 + (size_t)(it * 32) * K);
            }
        }

        // 4 k-steps of 8 over the 32-wide tile.
        #pragma unroll
        for (int ks = 0; ks < 4; ++ks) {
            const int k4a = ks * 2;
            const int k4b = ks * 2 + 1;
            const int kk  = lane & 3;
            const int g   = lane >> 2;

            uint32_t af[4][4];
            #pragma unroll
            for (int im = 0; im < 4; ++im) {
                const int m0 = wm * 64 + im * 16 + g;
                af[im][0] = Asw[(k4a * 128 + ((m0    ) ^ k4a)) * 4 + kk];
                af[im][1] = Asw[(k4a * 128 + ((m0 + 8) ^ k4a)) * 4 + kk];
                af[im][2] = Asw[(k4b * 128 + ((m0    ) ^ k4b)) * 4 + kk];
                af[im][3] = Asw[(k4b * 128 + ((m0 + 8) ^ k4b)) * 4 + kk];
            }
            uint32_t bf[4][2];
            #pragma unroll
            for (int jn = 0; jn < 4; ++jn) {
                const int n0 = wn * 32 + jn * 8 + g;
                bf[jn][0] = Bsw[(k4a * 128 + (n0 ^ k4a)) * 4 + kk];
                bf[jn][1] = Bsw[(k4b * 128 + (n0 ^ k4b)) * 4 + kk];
            }
            #pragma unroll
            for (int im = 0; im < 4; ++im)
                #pragma unroll
                for (int jn = 0; jn < 4; ++jn)
                    mma_tf32(acc[im][jn], af[im], bf[jn]);
        }
        __syncthreads();
    }

    // Epilogue: fragment layout -> global (float2 per half-row).
    const int g  = lane >> 2;
    const int q2 = (lane & 3) * 2;
    #pragma unroll
    for (int im = 0; im < 4; ++im) {
        const size_t row0 = mBase + wm * 64 + im * 16 + g;
        #pragma unroll
        for (int jn = 0; jn < 4; ++jn) {
            const size_t col0 = nBase + wn * 32 + jn * 8 + q2;
            *(float2*)&C[row0 * (size_t)N + col0] =
                make_float2(acc[im][jn][0], acc[im][jn][1]);
            *(float2*)&C[(row0 + 8) * (size_t)N + col0] =
                make_float2(acc[im][jn][2], acc[im][jn][3]);
        }
    }
}

// Elementwise: cumsum over t, silu, delta, closed-form Hadamard combine.
// Reads g_G (gate proj) and g_U (up proj), writes C in place into g_G.
__global__ void combine_kernel()
{
    const size_t total  = (size_t)BSROWS * INTER;  // 1024 * 5504
    const size_t stride = total;                   // distance between t-slabs
    size_t idx = (size_t)blockIdx.x * blockDim.x + threadIdx.x;
    if (idx >= total) return;

    float gv[TSTEPS], uv[TSTEPS];
    #pragma unroll
    for (int t = 0; t < TSTEPS; ++t) {
        gv[t] = g_G[idx + (size_t)t * stride];
        uv[t] = g_U[idx + (size_t)t * stride];
    }

    float X = 0.f, Yprev = 0.f, SB = 0.f;
    float A[TSTEPS];
    #pragma unroll
    for (int t = 0; t < TSTEPS; ++t) {
        X += gv[t];
        const float Y = X / (1.f + expf(-X));  // silu
        A[t] = Y - Yprev;
        Yprev = Y;
        SB += uv[t];
    }
    const float SA = Yprev;  // telescoping: sum_t A[t] = Y[T-1]

    #pragma unroll
    for (int t = 0; t < TSTEPS; ++t)
        g_G[idx + (size_t)t * stride] = 0.5f * (A[t] * SB + uv[t] * SA);
}

extern "C" void kernel_launch(void* const* d_in, const int* in_sizes, int n_in,
                              void* d_out, int out_size)
{
    const float* x      = (const float*)d_in[0];
    const float* w_gate = (const float*)d_in[1];
    const float* w_up   = (const float*)d_in[2];
    const float* w_down = (const float*)d_in[3];
    float* out = (float*)d_out;
    (void)in_sizes; (void)n_in; (void)out_size;

    float *dG = nullptr, *dU = nullptr;
    cudaGetSymbolAddress((void**)&dG, g_G);
    cudaGetSymbolAddress((void**)&dU, g_U);

    const dim3 blk(256);

    // Gate and up projections: (4096 x 5504) = x (4096 x 2048) @ W^T
    const dim3 grid1(INTER / 128, MROWS / 128);
    gemm_tn_kernel<<<grid1, blk>>>(x, w_gate, dG, HIDDEN, INTER);
    gemm_tn_kernel<<<grid1, blk>>>(x, w_up,   dU, HIDDEN, INTER);

    // Membrane accumulation + silu + Hadamard closed form (C -> g_G).
    const size_t total = (size_t)BSROWS * INTER;
    combine_kernel<<<(unsigned)((total + 255) / 256), 256>>>();

    // Down projection: (4096 x 2048) = C (4096 x 5504) @ w_down^T
    const dim3 grid2(HIDDEN / 128, MROWS / 128);
    gemm_tn_kernel<<<grid2, blk>>>(dG, w_down, out, INTER, HIDDEN);
}